// round 1
// baseline (speedup 1.0000x reference)
#include <cuda_runtime.h>
#include <math.h>
#include <stdint.h>

#define BB  4
#define LL  4096
#define DMm 512
#define DIi 1024
#define DSs 16
#define DCc 4
#define DTRr 32
#define MT  (BB*LL)   /* 16384 rows */

// ---------------- scratch (static device globals; no runtime alloc) -------------
__device__ float g_xT  [MT * DMm];        // x transposed to [m, DM]
__device__ float g_xz  [MT * 2 * DIi];    // in_proj output [m, 2048]
__device__ float g_xc  [MT * DIi];        // conv1d+silu output
__device__ float g_xdbl[MT * 64];         // x_proj output (dt_raw|B|C)
__device__ float g_dt  [MT * DIi];        // softplus dt
__device__ float g_y   [MT * DIi];        // scan output (fused epilogue)
__device__ float g_o1  [MT * DMm];        // out_proj output
__device__ float g_o2  [MT * DMm];        // 1x1 conv + gelu output
__device__ float g_red [8];               // per-b sum / sumsq
__device__ float g_stat[8];               // per-b mu / rstd

// ---------------- helpers --------------------------------------------------------
__device__ __forceinline__ float softplus_f(float x) {
    return x > 20.f ? x : log1pf(__expf(x));
}
__device__ __forceinline__ float gelu_f(float x) {
    return 0.5f * x * (1.f + erff(x * 0.70710678118654752f));
}
__device__ __forceinline__ float silu_f(float x) {
    return x / (1.f + __expf(-x));
}

// ---------------- 0. transpose x [B,DM,L] -> xT [m, DM] --------------------------
__global__ void k_transpose_x(const float* __restrict__ x) {
    __shared__ float t[32][33];
    int b  = blockIdx.z;
    int l0 = blockIdx.x * 32, d0 = blockIdx.y * 32;
    int tx = threadIdx.x, ty = threadIdx.y;            // block (32,8)
#pragma unroll
    for (int i = 0; i < 32; i += 8)
        t[ty + i][tx] = x[((size_t)b * DMm + d0 + ty + i) * LL + l0 + tx];
    __syncthreads();
#pragma unroll
    for (int i = 0; i < 32; i += 8)
        g_xT[((size_t)b * LL + l0 + ty + i) * DMm + d0 + tx] = t[tx][ty + i];
}

// ---------------- generic SGEMM: C[m,n] = sum_k A[m,k]*W[n,k] (+epilogue) --------
// BM=128, BN=64, BK=16, 256 threads, 8x4 per thread.
// EPI: 0 = none, 1 = +bias then softplus, 2 = +bias then exact GELU
template <int EPI>
__global__ void __launch_bounds__(256)
k_gemm(const float* __restrict__ A, int lda,
       const float* __restrict__ W,
       float* __restrict__ C, int N, int K,
       const float* __restrict__ bias) {
    __shared__ float As[16 * 129];
    __shared__ float Bs[16 * 65];
    int tid = threadIdx.x;
    int m0 = blockIdx.y * 128, n0 = blockIdx.x * 64;
    int tx = tid & 15, ty = tid >> 4;
    int kl = tid & 15;      // k-in-tile for loads
    int rl = tid >> 4;      // row base for loads

    float acc[8][4];
#pragma unroll
    for (int q = 0; q < 8; q++)
#pragma unroll
        for (int r = 0; r < 4; r++) acc[q][r] = 0.f;

    for (int k0 = 0; k0 < K; k0 += 16) {
#pragma unroll
        for (int p = 0; p < 8; p++) {
            int i = rl + p * 16;
            As[kl * 129 + i] = A[(size_t)(m0 + i) * lda + k0 + kl];
        }
#pragma unroll
        for (int p = 0; p < 4; p++) {
            int j = rl + p * 16;
            Bs[kl * 65 + j] = W[(size_t)(n0 + j) * K + k0 + kl];
        }
        __syncthreads();
#pragma unroll
        for (int kk = 0; kk < 16; kk++) {
            float a[8], bv[4];
#pragma unroll
            for (int q = 0; q < 8; q++) a[q] = As[kk * 129 + ty + q * 16];
#pragma unroll
            for (int r = 0; r < 4; r++) bv[r] = Bs[kk * 65 + tx + r * 16];
#pragma unroll
            for (int q = 0; q < 8; q++)
#pragma unroll
                for (int r = 0; r < 4; r++)
                    acc[q][r] = fmaf(a[q], bv[r], acc[q][r]);
        }
        __syncthreads();
    }
#pragma unroll
    for (int q = 0; q < 8; q++) {
        int m = m0 + ty + q * 16;
#pragma unroll
        for (int r = 0; r < 4; r++) {
            int n = n0 + tx + r * 16;
            float v = acc[q][r];
            if (EPI == 1) v = softplus_f(v + bias[n]);
            if (EPI == 2) v = gelu_f(v + bias[n]);
            C[(size_t)m * N + n] = v;
        }
    }
}

// ---------------- 2. causal depthwise conv1d + silu ------------------------------
__global__ void k_conv1d_silu(const float* __restrict__ w, const float* __restrict__ bias) {
    int idx = blockIdx.x * blockDim.x + threadIdx.x;   // over MT*DI
    int d = idx & (DIi - 1);
    int m = idx >> 10;
    int l = m & (LL - 1);
    float acc = bias[d];
#pragma unroll
    for (int k = 0; k < DCc; k++) {
        int ls = l - (DCc - 1) + k;
        if (ls >= 0)
            acc = fmaf(w[d * DCc + k], g_xz[(size_t)(m - (DCc - 1) + k) * 2 * DIi + d], acc);
    }
    g_xc[idx] = silu_f(acc);
}

// ---------------- 5. selective scan, fused (+D*xc)*silu(z) epilogue --------------
// One lane per (chain, state): chain = (b,d), 16 lanes per chain, 2 chains/warp.
__global__ void k_scan(const float* __restrict__ A_log, const float* __restrict__ Dp) {
    int t = blockIdx.x * blockDim.x + threadIdx.x;     // 65536 threads exactly
    int n = t & 15;
    int chain = t >> 4;
    int b = chain >> 10;
    int d = chain & (DIi - 1);

    float a  = -__expf(A_log[d * DSs + n]);
    float Dd = Dp[d];
    float h  = 0.f;

    const float* dt_p = g_dt   + (size_t)b * LL * DIi + d;
    const float* xc_p = g_xc   + (size_t)b * LL * DIi + d;
    const float* bd_p = g_xdbl + (size_t)b * LL * 64;
    const float* z_p  = g_xz   + (size_t)b * LL * 2 * DIi + DIi + d;
    float*       y_p  = g_y    + (size_t)b * LL * DIi + d;

    for (int l = 0; l < LL; l++) {
        float dt = dt_p[(size_t)l * DIi];
        float xv = xc_p[(size_t)l * DIi];
        float bn = bd_p[l * 64 + DTRr + n];
        float cn = bd_p[l * 64 + DTRr + DSs + n];
        float dA = __expf(dt * a);
        h = fmaf(dA, h, dt * xv * bn);
        float p = h * cn;
        p += __shfl_xor_sync(0xffffffffu, p, 8);
        p += __shfl_xor_sync(0xffffffffu, p, 4);
        p += __shfl_xor_sync(0xffffffffu, p, 2);
        p += __shfl_xor_sync(0xffffffffu, p, 1);
        if (n == 0) {
            float zz = z_p[(size_t)l * 2 * DIi];
            y_p[(size_t)l * DIi] = (p + Dd * xv) * silu_f(zz);
        }
    }
}

// ---------------- GroupNorm(1, DM) over (C,L) per sample -------------------------
__global__ void k_gn_zero() { if (threadIdx.x < 8) g_red[threadIdx.x] = 0.f; }

__global__ void k_gn_reduce() {
    int b = blockIdx.y;
    const float* p = g_o2 + (size_t)b * LL * DMm;
    float s = 0.f, s2 = 0.f;
    for (int i = blockIdx.x * blockDim.x + threadIdx.x; i < LL * DMm;
         i += gridDim.x * blockDim.x) {
        float v = p[i];
        s += v; s2 += v * v;
    }
    __shared__ float sh0[256], sh1[256];
    sh0[threadIdx.x] = s; sh1[threadIdx.x] = s2;
    __syncthreads();
    for (int o = 128; o > 0; o >>= 1) {
        if (threadIdx.x < o) {
            sh0[threadIdx.x] += sh0[threadIdx.x + o];
            sh1[threadIdx.x] += sh1[threadIdx.x + o];
        }
        __syncthreads();
    }
    if (threadIdx.x == 0) {
        atomicAdd(&g_red[b], sh0[0]);
        atomicAdd(&g_red[4 + b], sh1[0]);
    }
}

__global__ void k_gn_finalize() {
    int b = threadIdx.x;
    if (b < 4) {
        float nInv = 1.f / (float)(LL * DMm);
        float mu = g_red[b] * nInv;
        float var = g_red[4 + b] * nInv - mu * mu;
        g_stat[b] = mu;
        g_stat[4 + b] = rsqrtf(var + 1e-5f);
    }
}

// normalize + affine + transpose back to [B, DM, L]
__global__ void k_gn_write(float* __restrict__ out,
                           const float* __restrict__ gamma,
                           const float* __restrict__ beta) {
    __shared__ float t[32][33];
    int b = blockIdx.z;
    float mu = g_stat[b], rs = g_stat[4 + b];
    int l0 = blockIdx.x * 32, c0 = blockIdx.y * 32;
    int tx = threadIdx.x, ty = threadIdx.y;            // block (32,8)
#pragma unroll
    for (int i = 0; i < 32; i += 8)
        t[ty + i][tx] = g_o2[((size_t)b * LL + l0 + ty + i) * DMm + c0 + tx];
    __syncthreads();
#pragma unroll
    for (int i = 0; i < 32; i += 8) {
        int c = c0 + ty + i;
        out[((size_t)b * DMm + c) * LL + l0 + tx] =
            (t[tx][ty + i] - mu) * rs * gamma[c] + beta[c];
    }
}

// ---------------- host launcher ---------------------------------------------------
extern "C" void kernel_launch(void* const* d_in, const int* in_sizes, int n_in,
                              void* d_out, int out_size) {
    const float* x         = (const float*)d_in[0];
    const float* in_proj_w = (const float*)d_in[1];
    const float* conv1d_w  = (const float*)d_in[2];
    const float* conv1d_b  = (const float*)d_in[3];
    const float* x_proj_w  = (const float*)d_in[4];
    const float* dt_proj_w = (const float*)d_in[5];
    const float* dt_proj_b = (const float*)d_in[6];
    const float* A_log     = (const float*)d_in[7];
    const float* Dp        = (const float*)d_in[8];
    const float* out_proj_w= (const float*)d_in[9];
    const float* conv_w    = (const float*)d_in[10];
    const float* conv_b    = (const float*)d_in[11];
    const float* gamma     = (const float*)d_in[12];
    const float* beta      = (const float*)d_in[13];
    float* out = (float*)d_out;

    // symbol addresses (not stream ops; graph-capture-safe)
    static float *p_xT = nullptr, *p_xz, *p_xc, *p_xdbl, *p_dt, *p_y, *p_o1, *p_o2;
    if (!p_xT) {
        cudaGetSymbolAddress((void**)&p_xT,   g_xT);
        cudaGetSymbolAddress((void**)&p_xz,   g_xz);
        cudaGetSymbolAddress((void**)&p_xc,   g_xc);
        cudaGetSymbolAddress((void**)&p_xdbl, g_xdbl);
        cudaGetSymbolAddress((void**)&p_dt,   g_dt);
        cudaGetSymbolAddress((void**)&p_y,    g_y);
        cudaGetSymbolAddress((void**)&p_o1,   g_o1);
        cudaGetSymbolAddress((void**)&p_o2,   g_o2);
    }

    dim3 tb(32, 8);
    // 0. transpose x -> xT [m, DM]
    k_transpose_x<<<dim3(LL / 32, DMm / 32, BB), tb>>>(x);

    // 1. xz = xT @ in_proj_w^T   [m, 2048]
    k_gemm<0><<<dim3(2 * DIi / 64, MT / 128), 256>>>(p_xT, DMm, in_proj_w, p_xz, 2 * DIi, DMm, nullptr);

    // 2. causal depthwise conv1d + silu -> xc
    k_conv1d_silu<<<(MT * DIi) / 256, 256>>>(conv1d_w, conv1d_b);

    // 3. x_dbl = xc @ x_proj_w^T  [m, 64]
    k_gemm<0><<<dim3(64 / 64, MT / 128), 256>>>(p_xc, DIi, x_proj_w, p_xdbl, 64, DIi, nullptr);

    // 4. dt = softplus(x_dbl[:, :32] @ dt_proj_w^T + b)  [m, 1024]
    k_gemm<1><<<dim3(DIi / 64, MT / 128), 256>>>(p_xdbl, 64, dt_proj_w, p_dt, DIi, DTRr, dt_proj_b);

    // 5. selective scan (fused +D*xc, *silu(z)) -> y [m, 1024]
    k_scan<<<(BB * DIi * DSs) / 256, 256>>>(A_log, Dp);

    // 6. o1 = y @ out_proj_w^T  [m, 512]
    k_gemm<0><<<dim3(DMm / 64, MT / 128), 256>>>(p_y, DIi, out_proj_w, p_o1, DMm, DIi, nullptr);

    // 7. o2 = gelu(o1 @ conv_w^T + conv_b)  [m, 512]
    k_gemm<2><<<dim3(DMm / 64, MT / 128), 256>>>(p_o1, DMm, conv_w, p_o2, DMm, DMm, conv_b);

    // 8. GroupNorm stats + normalize + affine + transpose to [B, DM, L]
    k_gn_zero<<<1, 32>>>();
    k_gn_reduce<<<dim3(128, BB), 256>>>();
    k_gn_finalize<<<1, 32>>>();
    k_gn_write<<<dim3(LL / 32, DMm / 32, BB), tb>>>(out, gamma, beta);
}

// round 2
// speedup vs baseline: 1.2778x; 1.2778x over previous
#include <cuda_runtime.h>
#include <math.h>
#include <stdint.h>

#define BB  4
#define LL  4096
#define DMm 512
#define DIi 1024
#define DSs 16
#define DCc 4
#define DTRr 32
#define MT  (BB*LL)   /* 16384 rows */

// ---------------- scratch (static device globals; no runtime alloc) -------------
__device__ float g_xT  [MT * DMm];        // x transposed to [m, DM]
__device__ float g_xz  [MT * 2 * DIi];    // in_proj output [m, 2048]
__device__ float g_xc  [MT * DIi];        // conv1d+silu output
__device__ float g_xdbl[MT * 64];         // x_proj output (dt_raw|B|C)
__device__ float g_dt  [MT * DIi];        // softplus dt
__device__ float g_y   [MT * DIi];        // scan output (fused epilogue)
__device__ float g_o1  [MT * DMm];        // out_proj output
__device__ float g_o2  [MT * DMm];        // 1x1 conv + gelu output
__device__ float g_red [8];               // per-b sum / sumsq
__device__ float g_stat[8];               // per-b mu / rstd

// ---------------- helpers --------------------------------------------------------
__device__ __forceinline__ float softplus_f(float x) {
    return x > 20.f ? x : log1pf(__expf(x));
}
__device__ __forceinline__ float gelu_f(float x) {
    return 0.5f * x * (1.f + erff(x * 0.70710678118654752f));
}
__device__ __forceinline__ float silu_f(float x) {
    return x / (1.f + __expf(-x));
}
__device__ __forceinline__ unsigned f2tf32(float f) {
    unsigned r;
    asm("cvt.rna.tf32.f32 %0, %1;" : "=r"(r) : "f"(f));
    return r;
}
__device__ __forceinline__ void mma_tf32(float* d, const unsigned* a, const unsigned* b) {
    asm volatile(
        "mma.sync.aligned.m16n8k8.row.col.f32.tf32.tf32.f32 "
        "{%0,%1,%2,%3}, {%4,%5,%6,%7}, {%8,%9}, {%0,%1,%2,%3};"
        : "+f"(d[0]), "+f"(d[1]), "+f"(d[2]), "+f"(d[3])
        : "r"(a[0]), "r"(a[1]), "r"(a[2]), "r"(a[3]), "r"(b[0]), "r"(b[1]));
}

// ---------------- 0. transpose x [B,DM,L] -> xT [m, DM] --------------------------
__global__ void k_transpose_x(const float* __restrict__ x) {
    __shared__ float t[32][33];
    int b  = blockIdx.z;
    int l0 = blockIdx.x * 32, d0 = blockIdx.y * 32;
    int tx = threadIdx.x, ty = threadIdx.y;            // block (32,8)
#pragma unroll
    for (int i = 0; i < 32; i += 8)
        t[ty + i][tx] = x[((size_t)b * DMm + d0 + ty + i) * LL + l0 + tx];
    __syncthreads();
#pragma unroll
    for (int i = 0; i < 32; i += 8)
        g_xT[((size_t)b * LL + l0 + ty + i) * DMm + d0 + tx] = t[tx][ty + i];
}

// ---------------- tf32 tensor-core GEMM: C[m,n] = sum_k A[m,k]*W[n,k] ------------
// BM=128, BK=16, BN template (128 or 64). 256 threads, 8 warps.
// smem m-major [rows][BK+4] (stride 20 => conflict-free fragment loads).
// EPI: 0 none, 1 +bias softplus, 2 +bias exact GELU.
#define BMt 128
#define BKt 16
#define BKP 20

template <int BN, int EPI>
__global__ void __launch_bounds__(256)
k_gemm_tc(const float* __restrict__ A, int lda,
          const float* __restrict__ W,
          float* __restrict__ C, int N, int K,
          const float* __restrict__ bias) {
    constexpr int WARPS_N = (BN == 128) ? 4 : 2;
    constexpr int WTM = (BN == 128) ? 64 : 32;
    constexpr int WTN = 32;
    constexpr int MTl = WTM / 16;   // m16 tiles per warp
    constexpr int NTl = WTN / 8;    // n8 tiles per warp
    constexpr int BPASS = BN / 64;  // B staging passes

    __shared__ float As[2][BMt][BKP];
    __shared__ float Bs[2][BN][BKP];

    int tid = threadIdx.x;
    int warp = tid >> 5, lane = tid & 31;
    int wm = warp / WARPS_N, wn = warp % WARPS_N;
    int g = lane >> 2, t = lane & 3;
    int m0 = blockIdx.y * BMt, n0 = blockIdx.x * BN;

    int srow = tid >> 2;          // 0..63
    int scol = (tid & 3) * 4;     // k offset (float4)

    const float* Ag = A + (size_t)(m0 + srow) * lda + scol;
    const float* Bg = W + (size_t)(n0 + srow) * K + scol;

    float acc[MTl][NTl][4];
#pragma unroll
    for (int i = 0; i < MTl; i++)
#pragma unroll
        for (int j = 0; j < NTl; j++)
#pragma unroll
            for (int r = 0; r < 4; r++) acc[i][j][r] = 0.f;

    float4 ra[2], rb[BPASS];

    // prologue: load tile 0
#pragma unroll
    for (int p = 0; p < 2; p++) ra[p] = *(const float4*)(Ag + (size_t)(64 * p) * lda);
#pragma unroll
    for (int p = 0; p < BPASS; p++) rb[p] = *(const float4*)(Bg + (size_t)(64 * p) * K);
#pragma unroll
    for (int p = 0; p < 2; p++) {
        float* d = &As[0][srow + 64 * p][scol];
        d[0] = __uint_as_float(f2tf32(ra[p].x));
        d[1] = __uint_as_float(f2tf32(ra[p].y));
        d[2] = __uint_as_float(f2tf32(ra[p].z));
        d[3] = __uint_as_float(f2tf32(ra[p].w));
    }
#pragma unroll
    for (int p = 0; p < BPASS; p++) {
        float* d = &Bs[0][srow + 64 * p][scol];
        d[0] = __uint_as_float(f2tf32(rb[p].x));
        d[1] = __uint_as_float(f2tf32(rb[p].y));
        d[2] = __uint_as_float(f2tf32(rb[p].z));
        d[3] = __uint_as_float(f2tf32(rb[p].w));
    }
    __syncthreads();

    int nIter = K / BKt;
    int buf = 0;
    for (int it = 0; it < nIter; it++) {
        if (it + 1 < nIter) {
            int k0 = (it + 1) * BKt;
#pragma unroll
            for (int p = 0; p < 2; p++) ra[p] = *(const float4*)(Ag + (size_t)(64 * p) * lda + k0);
#pragma unroll
            for (int p = 0; p < BPASS; p++) rb[p] = *(const float4*)(Bg + (size_t)(64 * p) * K + k0);
        }
        // compute on buf: 2 k-steps of 8
#pragma unroll
        for (int kk = 0; kk < 2; kk++) {
            unsigned af[MTl][4], bf[NTl][2];
#pragma unroll
            for (int i = 0; i < MTl; i++) {
                int m = wm * WTM + i * 16;
                af[i][0] = __float_as_uint(As[buf][m + g][kk * 8 + t]);
                af[i][1] = __float_as_uint(As[buf][m + g + 8][kk * 8 + t]);
                af[i][2] = __float_as_uint(As[buf][m + g][kk * 8 + t + 4]);
                af[i][3] = __float_as_uint(As[buf][m + g + 8][kk * 8 + t + 4]);
            }
#pragma unroll
            for (int j = 0; j < NTl; j++) {
                int n = wn * WTN + j * 8;
                bf[j][0] = __float_as_uint(Bs[buf][n + g][kk * 8 + t]);
                bf[j][1] = __float_as_uint(Bs[buf][n + g][kk * 8 + t + 4]);
            }
#pragma unroll
            for (int i = 0; i < MTl; i++)
#pragma unroll
                for (int j = 0; j < NTl; j++)
                    mma_tf32(acc[i][j], af[i], bf[j]);
        }
        if (it + 1 < nIter) {
#pragma unroll
            for (int p = 0; p < 2; p++) {
                float* d = &As[buf ^ 1][srow + 64 * p][scol];
                d[0] = __uint_as_float(f2tf32(ra[p].x));
                d[1] = __uint_as_float(f2tf32(ra[p].y));
                d[2] = __uint_as_float(f2tf32(ra[p].z));
                d[3] = __uint_as_float(f2tf32(ra[p].w));
            }
#pragma unroll
            for (int p = 0; p < BPASS; p++) {
                float* d = &Bs[buf ^ 1][srow + 64 * p][scol];
                d[0] = __uint_as_float(f2tf32(rb[p].x));
                d[1] = __uint_as_float(f2tf32(rb[p].y));
                d[2] = __uint_as_float(f2tf32(rb[p].z));
                d[3] = __uint_as_float(f2tf32(rb[p].w));
            }
            __syncthreads();
            buf ^= 1;
        }
    }

    // epilogue: c0:(g,2t) c1:(g,2t+1) c2:(g+8,2t) c3:(g+8,2t+1)
#pragma unroll
    for (int i = 0; i < MTl; i++) {
#pragma unroll
        for (int j = 0; j < NTl; j++) {
            int m = m0 + wm * WTM + i * 16 + g;
            int n = n0 + wn * WTN + j * 8 + 2 * t;
            float b0 = 0.f, b1 = 0.f;
            if (EPI != 0) { b0 = bias[n]; b1 = bias[n + 1]; }
            float v0 = acc[i][j][0], v1 = acc[i][j][1];
            float v2 = acc[i][j][2], v3 = acc[i][j][3];
            if (EPI == 1) { v0 = softplus_f(v0 + b0); v1 = softplus_f(v1 + b1);
                            v2 = softplus_f(v2 + b0); v3 = softplus_f(v3 + b1); }
            if (EPI == 2) { v0 = gelu_f(v0 + b0); v1 = gelu_f(v1 + b1);
                            v2 = gelu_f(v2 + b0); v3 = gelu_f(v3 + b1); }
            *(float2*)&C[(size_t)m * N + n]       = make_float2(v0, v1);
            *(float2*)&C[(size_t)(m + 8) * N + n] = make_float2(v2, v3);
        }
    }
}

// ---------------- 2. causal depthwise conv1d + silu ------------------------------
__global__ void k_conv1d_silu(const float* __restrict__ w, const float* __restrict__ bias) {
    int idx = blockIdx.x * blockDim.x + threadIdx.x;   // over MT*DI
    int d = idx & (DIi - 1);
    int m = idx >> 10;
    int l = m & (LL - 1);
    float acc = bias[d];
#pragma unroll
    for (int k = 0; k < DCc; k++) {
        int ls = l - (DCc - 1) + k;
        if (ls >= 0)
            acc = fmaf(w[d * DCc + k], g_xz[(size_t)(m - (DCc - 1) + k) * 2 * DIi + d], acc);
    }
    g_xc[idx] = silu_f(acc);
}

// ---------------- 5. selective scan, fused (+D*xc)*silu(z) epilogue --------------
__global__ void k_scan(const float* __restrict__ A_log, const float* __restrict__ Dp) {
    int t = blockIdx.x * blockDim.x + threadIdx.x;     // 65536 threads exactly
    int n = t & 15;
    int chain = t >> 4;
    int b = chain >> 10;
    int d = chain & (DIi - 1);

    float a  = -__expf(A_log[d * DSs + n]);
    float Dd = Dp[d];
    float h  = 0.f;

    const float* dt_p = g_dt   + (size_t)b * LL * DIi + d;
    const float* xc_p = g_xc   + (size_t)b * LL * DIi + d;
    const float* bd_p = g_xdbl + (size_t)b * LL * 64;
    const float* z_p  = g_xz   + (size_t)b * LL * 2 * DIi + DIi + d;
    float*       y_p  = g_y    + (size_t)b * LL * DIi + d;

    for (int l = 0; l < LL; l++) {
        float dt = dt_p[(size_t)l * DIi];
        float xv = xc_p[(size_t)l * DIi];
        float bn = bd_p[l * 64 + DTRr + n];
        float cn = bd_p[l * 64 + DTRr + DSs + n];
        float dA = __expf(dt * a);
        h = fmaf(dA, h, dt * xv * bn);
        float p = h * cn;
        p += __shfl_xor_sync(0xffffffffu, p, 8);
        p += __shfl_xor_sync(0xffffffffu, p, 4);
        p += __shfl_xor_sync(0xffffffffu, p, 2);
        p += __shfl_xor_sync(0xffffffffu, p, 1);
        if (n == 0) {
            float zz = z_p[(size_t)l * 2 * DIi];
            y_p[(size_t)l * DIi] = (p + Dd * xv) * silu_f(zz);
        }
    }
}

// ---------------- GroupNorm(1, DM) over (C,L) per sample -------------------------
__global__ void k_gn_zero() { if (threadIdx.x < 8) g_red[threadIdx.x] = 0.f; }

__global__ void k_gn_reduce() {
    int b = blockIdx.y;
    const float* p = g_o2 + (size_t)b * LL * DMm;
    float s = 0.f, s2 = 0.f;
    for (int i = blockIdx.x * blockDim.x + threadIdx.x; i < LL * DMm;
         i += gridDim.x * blockDim.x) {
        float v = p[i];
        s += v; s2 += v * v;
    }
    __shared__ float sh0[256], sh1[256];
    sh0[threadIdx.x] = s; sh1[threadIdx.x] = s2;
    __syncthreads();
    for (int o = 128; o > 0; o >>= 1) {
        if (threadIdx.x < o) {
            sh0[threadIdx.x] += sh0[threadIdx.x + o];
            sh1[threadIdx.x] += sh1[threadIdx.x + o];
        }
        __syncthreads();
    }
    if (threadIdx.x == 0) {
        atomicAdd(&g_red[b], sh0[0]);
        atomicAdd(&g_red[4 + b], sh1[0]);
    }
}

__global__ void k_gn_finalize() {
    int b = threadIdx.x;
    if (b < 4) {
        float nInv = 1.f / (float)(LL * DMm);
        float mu = g_red[b] * nInv;
        float var = g_red[4 + b] * nInv - mu * mu;
        g_stat[b] = mu;
        g_stat[4 + b] = rsqrtf(var + 1e-5f);
    }
}

// normalize + affine + transpose back to [B, DM, L]
__global__ void k_gn_write(float* __restrict__ out,
                           const float* __restrict__ gamma,
                           const float* __restrict__ beta) {
    __shared__ float t[32][33];
    int b = blockIdx.z;
    float mu = g_stat[b], rs = g_stat[4 + b];
    int l0 = blockIdx.x * 32, c0 = blockIdx.y * 32;
    int tx = threadIdx.x, ty = threadIdx.y;            // block (32,8)
#pragma unroll
    for (int i = 0; i < 32; i += 8)
        t[ty + i][tx] = g_o2[((size_t)b * LL + l0 + ty + i) * DMm + c0 + tx];
    __syncthreads();
#pragma unroll
    for (int i = 0; i < 32; i += 8) {
        int c = c0 + ty + i;
        out[((size_t)b * DMm + c) * LL + l0 + tx] =
            (t[tx][ty + i] - mu) * rs * gamma[c] + beta[c];
    }
}

// ---------------- host launcher ---------------------------------------------------
extern "C" void kernel_launch(void* const* d_in, const int* in_sizes, int n_in,
                              void* d_out, int out_size) {
    const float* x         = (const float*)d_in[0];
    const float* in_proj_w = (const float*)d_in[1];
    const float* conv1d_w  = (const float*)d_in[2];
    const float* conv1d_b  = (const float*)d_in[3];
    const float* x_proj_w  = (const float*)d_in[4];
    const float* dt_proj_w = (const float*)d_in[5];
    const float* dt_proj_b = (const float*)d_in[6];
    const float* A_log     = (const float*)d_in[7];
    const float* Dp        = (const float*)d_in[8];
    const float* out_proj_w= (const float*)d_in[9];
    const float* conv_w    = (const float*)d_in[10];
    const float* conv_b    = (const float*)d_in[11];
    const float* gamma     = (const float*)d_in[12];
    const float* beta      = (const float*)d_in[13];
    float* out = (float*)d_out;

    static float *p_xT = nullptr, *p_xz, *p_xc, *p_xdbl, *p_dt, *p_y, *p_o1, *p_o2;
    if (!p_xT) {
        cudaGetSymbolAddress((void**)&p_xT,   g_xT);
        cudaGetSymbolAddress((void**)&p_xz,   g_xz);
        cudaGetSymbolAddress((void**)&p_xc,   g_xc);
        cudaGetSymbolAddress((void**)&p_xdbl, g_xdbl);
        cudaGetSymbolAddress((void**)&p_dt,   g_dt);
        cudaGetSymbolAddress((void**)&p_y,    g_y);
        cudaGetSymbolAddress((void**)&p_o1,   g_o1);
        cudaGetSymbolAddress((void**)&p_o2,   g_o2);
    }

    dim3 tb(32, 8);
    // 0. transpose x -> xT [m, DM]
    k_transpose_x<<<dim3(LL / 32, DMm / 32, BB), tb>>>(x);

    // 1. xz = xT @ in_proj_w^T   [m, 2048]
    k_gemm_tc<128, 0><<<dim3(2 * DIi / 128, MT / 128), 256>>>(p_xT, DMm, in_proj_w, p_xz, 2 * DIi, DMm, nullptr);

    // 2. causal depthwise conv1d + silu -> xc
    k_conv1d_silu<<<(MT * DIi) / 256, 256>>>(conv1d_w, conv1d_b);

    // 3. x_dbl = xc @ x_proj_w^T  [m, 64]
    k_gemm_tc<64, 0><<<dim3(64 / 64, MT / 128), 256>>>(p_xc, DIi, x_proj_w, p_xdbl, 64, DIi, nullptr);

    // 4. dt = softplus(x_dbl[:, :32] @ dt_proj_w^T + b)  [m, 1024]
    k_gemm_tc<128, 1><<<dim3(DIi / 128, MT / 128), 256>>>(p_xdbl, 64, dt_proj_w, p_dt, DIi, DTRr, dt_proj_b);

    // 5. selective scan (fused +D*xc, *silu(z)) -> y [m, 1024]
    k_scan<<<(BB * DIi * DSs) / 256, 256>>>(A_log, Dp);

    // 6. o1 = y @ out_proj_w^T  [m, 512]
    k_gemm_tc<128, 0><<<dim3(DMm / 128, MT / 128), 256>>>(p_y, DIi, out_proj_w, p_o1, DMm, DIi, nullptr);

    // 7. o2 = gelu(o1 @ conv_w^T + conv_b)  [m, 512]
    k_gemm_tc<128, 2><<<dim3(DMm / 128, MT / 128), 256>>>(p_o1, DMm, conv_w, p_o2, DMm, DMm, conv_b);

    // 8. GroupNorm stats + normalize + affine + transpose to [B, DM, L]
    k_gn_zero<<<1, 32>>>();
    k_gn_reduce<<<dim3(128, BB), 256>>>();
    k_gn_finalize<<<1, 32>>>();
    k_gn_write<<<dim3(LL / 32, DMm / 32, BB), tb>>>(out, gamma, beta);
}

// round 3
// speedup vs baseline: 3.2440x; 2.5388x over previous
#include <cuda_runtime.h>
#include <math.h>
#include <stdint.h>

#define BB  4
#define LL  4096
#define DMm 512
#define DIi 1024
#define DSs 16
#define DCc 4
#define DTRr 32
#define MT  (BB*LL)   /* 16384 rows */
#define CH  16        /* scan chunks */
#define CS  (LL/CH)   /* 256 steps per chunk */

// ---------------- scratch (static device globals; no runtime alloc) -------------
__device__ float g_xT  [MT * DMm];        // x transposed to [m, DM]
__device__ float g_xz  [MT * 2 * DIi];    // in_proj output [m, 2048]
__device__ float g_xc  [MT * DIi];        // conv1d+silu output
__device__ float g_xdbl[MT * 64];         // x_proj output (dt_raw|B|C)
__device__ float g_dt  [MT * DIi];        // softplus dt
__device__ float g_y   [MT * DIi];        // scan output (fused epilogue)
__device__ float g_o1  [MT * DMm];        // out_proj output
__device__ float g_o2  [MT * DMm];        // 1x1 conv + gelu output
__device__ float g_S   [CH * BB * DIi * DSs];  // chunk scan endpoints
__device__ float g_P   [CH * BB * DIi * DSs];  // chunk transition products
__device__ float g_hi  [CH * BB * DIi * DSs];  // chunk initial states
__device__ float g_red [8];               // per-b sum / sumsq
__device__ float g_stat[8];               // per-b mu / rstd

// ---------------- helpers --------------------------------------------------------
__device__ __forceinline__ float softplus_f(float x) {
    return x > 20.f ? x : log1pf(__expf(x));
}
__device__ __forceinline__ float gelu_f(float x) {
    return 0.5f * x * (1.f + erff(x * 0.70710678118654752f));
}
__device__ __forceinline__ float silu_f(float x) {
    return x / (1.f + __expf(-x));
}
__device__ __forceinline__ unsigned f2tf32(float f) {
    unsigned r;
    asm("cvt.rna.tf32.f32 %0, %1;" : "=r"(r) : "f"(f));
    return r;
}
__device__ __forceinline__ void mma_tf32(float* d, const unsigned* a, const unsigned* b) {
    asm volatile(
        "mma.sync.aligned.m16n8k8.row.col.f32.tf32.tf32.f32 "
        "{%0,%1,%2,%3}, {%4,%5,%6,%7}, {%8,%9}, {%0,%1,%2,%3};"
        : "+f"(d[0]), "+f"(d[1]), "+f"(d[2]), "+f"(d[3])
        : "r"(a[0]), "r"(a[1]), "r"(a[2]), "r"(a[3]), "r"(b[0]), "r"(b[1]));
}
__device__ __forceinline__ void cp16(float* dst_smem, const float* src) {
    unsigned d = (unsigned)__cvta_generic_to_shared(dst_smem);
    asm volatile("cp.async.cg.shared.global [%0], [%1], 16;\n" :: "r"(d), "l"(src));
}
__device__ __forceinline__ void cp_commit() {
    asm volatile("cp.async.commit_group;\n");
}
template <int N>
__device__ __forceinline__ void cp_wait() {
    asm volatile("cp.async.wait_group %0;\n" :: "n"(N));
}

// ---------------- 0. transpose x [B,DM,L] -> xT [m, DM] --------------------------
__global__ void k_transpose_x(const float* __restrict__ x) {
    __shared__ float t[32][33];
    int b  = blockIdx.z;
    int l0 = blockIdx.x * 32, d0 = blockIdx.y * 32;
    int tx = threadIdx.x, ty = threadIdx.y;            // block (32,8)
#pragma unroll
    for (int i = 0; i < 32; i += 8)
        t[ty + i][tx] = x[((size_t)b * DMm + d0 + ty + i) * LL + l0 + tx];
    __syncthreads();
#pragma unroll
    for (int i = 0; i < 32; i += 8)
        g_xT[((size_t)b * LL + l0 + ty + i) * DMm + d0 + tx] = t[tx][ty + i];
}

// ---------- tf32 GEMM, cp.async 3-stage pipeline: C = A(m,k) * W(n,k)^T ----------
// smem m-major [rows][BKP=20] (conflict-free fragment loads). cvt to tf32 at
// fragment load. EPI: 0 none, 1 +bias softplus, 2 +bias exact GELU.
#define BKg  16
#define BKP  20
#define NSTG 3

template <int BM, int BN, int WM, int WN, int EPI>
__global__ void __launch_bounds__(256, 2)
k_gemm_ca(const float* __restrict__ A, int lda,
          const float* __restrict__ W,
          float* __restrict__ C, int N, int K,
          const float* __restrict__ bias) {
    constexpr int WTM = BM / WM, WTN = BN / WN;
    constexpr int MTl = WTM / 16, NTl = WTN / 8;
    constexpr int CA = BM / 64, CB = BN / 64;   // 16B chunks per thread per stage

    extern __shared__ float sm[];
    float* As = sm;                         // [NSTG][BM][BKP]
    float* Bs = sm + NSTG * BM * BKP;       // [NSTG][BN][BKP]

    int tid = threadIdx.x;
    int warp = tid >> 5, lane = tid & 31;
    int wm = warp / WN, wn = warp % WN;
    int g = lane >> 2, t = lane & 3;
    int m0 = blockIdx.y * BM, n0 = blockIdx.x * BN;

    float acc[MTl][NTl][4];
#pragma unroll
    for (int i = 0; i < MTl; i++)
#pragma unroll
        for (int j = 0; j < NTl; j++)
#pragma unroll
            for (int r = 0; r < 4; r++) acc[i][j][r] = 0.f;

    const int nIter = K / BKg;

    auto issue = [&](int s, int kt) {
        int k0 = kt * BKg;
#pragma unroll
        for (int i = 0; i < CA; i++) {
            int ch = tid + 256 * i;
            int r = ch >> 2, cc = (ch & 3) * 4;
            cp16(&As[(s * BM + r) * BKP + cc], A + (size_t)(m0 + r) * lda + k0 + cc);
        }
#pragma unroll
        for (int i = 0; i < CB; i++) {
            int ch = tid + 256 * i;
            int r = ch >> 2, cc = (ch & 3) * 4;
            cp16(&Bs[(s * BN + r) * BKP + cc], W + (size_t)(n0 + r) * K + k0 + cc);
        }
    };

    // prologue: stages 0..NSTG-2
#pragma unroll
    for (int s = 0; s < NSTG - 1; s++) {
        if (s < nIter) issue(s, s);
        cp_commit();
    }

    for (int it = 0; it < nIter; it++) {
        cp_wait<NSTG - 2>();
        __syncthreads();
        int nxt = it + NSTG - 1;
        if (nxt < nIter) issue(nxt % NSTG, nxt);
        cp_commit();

        const float* as = As + (it % NSTG) * BM * BKP;
        const float* bs = Bs + (it % NSTG) * BN * BKP;
#pragma unroll
        for (int kk = 0; kk < 2; kk++) {
            unsigned af[MTl][4], bf[NTl][2];
#pragma unroll
            for (int i = 0; i < MTl; i++) {
                int m = wm * WTM + i * 16;
                af[i][0] = f2tf32(as[(m + g) * BKP + kk * 8 + t]);
                af[i][1] = f2tf32(as[(m + g + 8) * BKP + kk * 8 + t]);
                af[i][2] = f2tf32(as[(m + g) * BKP + kk * 8 + t + 4]);
                af[i][3] = f2tf32(as[(m + g + 8) * BKP + kk * 8 + t + 4]);
            }
#pragma unroll
            for (int j = 0; j < NTl; j++) {
                int n = wn * WTN + j * 8;
                bf[j][0] = f2tf32(bs[(n + g) * BKP + kk * 8 + t]);
                bf[j][1] = f2tf32(bs[(n + g) * BKP + kk * 8 + t + 4]);
            }
#pragma unroll
            for (int i = 0; i < MTl; i++)
#pragma unroll
                for (int j = 0; j < NTl; j++)
                    mma_tf32(acc[i][j], af[i], bf[j]);
        }
    }

    // epilogue: c0:(g,2t) c1:(g,2t+1) c2:(g+8,2t) c3:(g+8,2t+1)
#pragma unroll
    for (int i = 0; i < MTl; i++) {
#pragma unroll
        for (int j = 0; j < NTl; j++) {
            int m = m0 + wm * WTM + i * 16 + g;
            int n = n0 + wn * WTN + j * 8 + 2 * t;
            float b0 = 0.f, b1 = 0.f;
            if (EPI != 0) { b0 = bias[n]; b1 = bias[n + 1]; }
            float v0 = acc[i][j][0], v1 = acc[i][j][1];
            float v2 = acc[i][j][2], v3 = acc[i][j][3];
            if (EPI == 1) { v0 = softplus_f(v0 + b0); v1 = softplus_f(v1 + b1);
                            v2 = softplus_f(v2 + b0); v3 = softplus_f(v3 + b1); }
            if (EPI == 2) { v0 = gelu_f(v0 + b0); v1 = gelu_f(v1 + b1);
                            v2 = gelu_f(v2 + b0); v3 = gelu_f(v3 + b1); }
            *(float2*)&C[(size_t)m * N + n]       = make_float2(v0, v1);
            *(float2*)&C[(size_t)(m + 8) * N + n] = make_float2(v2, v3);
        }
    }
}

// ---------------- 2. causal depthwise conv1d + silu ------------------------------
__global__ void k_conv1d_silu(const float* __restrict__ w, const float* __restrict__ bias) {
    int idx = blockIdx.x * blockDim.x + threadIdx.x;   // over MT*DI
    int d = idx & (DIi - 1);
    int m = idx >> 10;
    int l = m & (LL - 1);
    float acc = bias[d];
#pragma unroll
    for (int k = 0; k < DCc; k++) {
        int ls = l - (DCc - 1) + k;
        if (ls >= 0)
            acc = fmaf(w[d * DCc + k], g_xz[(size_t)(m - (DCc - 1) + k) * 2 * DIi + d], acc);
    }
    g_xc[idx] = silu_f(acc);
}

// ---------------- 5a. chunked scan pass A: per-chunk (S, P) ----------------------
__global__ void k_scanA(const float* __restrict__ A_log) {
    int t = blockIdx.x * blockDim.x + threadIdx.x;  // CH*4096*16 threads
    int n = t & 15;
    int chain = (t >> 4) & 4095;          // b*1024 + d
    int c = t >> 16;
    int b = chain >> 10;
    int d = chain & (DIi - 1);

    float a = -__expf(A_log[d * DSs + n]);
    int mb = b * LL + c * CS;

    const float* dt_p = g_dt   + (size_t)mb * DIi + d;
    const float* xc_p = g_xc   + (size_t)mb * DIi + d;
    const float* bd_p = g_xdbl + (size_t)mb * 64;

    float h = 0.f, sdt = 0.f;
    for (int l = 0; l < CS; l++) {
        float dt = dt_p[(size_t)l * DIi];
        float xv = xc_p[(size_t)l * DIi];
        float bn = bd_p[l * 64 + DTRr + n];
        h = fmaf(__expf(dt * a), h, dt * xv * bn);
        sdt += dt;
    }
    int o = (c * 4096 + chain) * DSs + n;
    g_S[o] = h;
    g_P[o] = __expf(a * sdt);
}

// ---------------- 5b. combine chunk states (serial over 16 chunks) ---------------
__global__ void k_scanC() {
    int t = blockIdx.x * blockDim.x + threadIdx.x;  // 65536 threads
    float h = 0.f;
#pragma unroll
    for (int c = 0; c < CH; c++) {
        int o = (c * 4096 << 4) + t;    // (c*4096 + chain)*16 + n == c*65536 + t
        g_hi[o] = h;
        h = g_S[o] + g_P[o] * h;
    }
}

// ---------------- 5c. chunked scan pass B: replay + y, fused epilogue ------------
__global__ void k_scanB(const float* __restrict__ A_log, const float* __restrict__ Dp) {
    int t = blockIdx.x * blockDim.x + threadIdx.x;
    int n = t & 15;
    int chain = (t >> 4) & 4095;
    int c = t >> 16;
    int b = chain >> 10;
    int d = chain & (DIi - 1);

    float a  = -__expf(A_log[d * DSs + n]);
    float Dd = Dp[d];
    float h  = g_hi[(c * 4096 + chain) * DSs + n];
    int mb = b * LL + c * CS;

    const float* dt_p = g_dt   + (size_t)mb * DIi + d;
    const float* xc_p = g_xc   + (size_t)mb * DIi + d;
    const float* bd_p = g_xdbl + (size_t)mb * 64;
    const float* z_p  = g_xz   + (size_t)mb * 2 * DIi + DIi + d;
    float*       y_p  = g_y    + (size_t)mb * DIi + d;

    for (int l = 0; l < CS; l++) {
        float dt = dt_p[(size_t)l * DIi];
        float xv = xc_p[(size_t)l * DIi];
        float bn = bd_p[l * 64 + DTRr + n];
        float cn = bd_p[l * 64 + DTRr + DSs + n];
        h = fmaf(__expf(dt * a), h, dt * xv * bn);
        float p = h * cn;
        p += __shfl_xor_sync(0xffffffffu, p, 8);
        p += __shfl_xor_sync(0xffffffffu, p, 4);
        p += __shfl_xor_sync(0xffffffffu, p, 2);
        p += __shfl_xor_sync(0xffffffffu, p, 1);
        if (n == 0) {
            float zz = z_p[(size_t)l * 2 * DIi];
            y_p[(size_t)l * DIi] = (p + Dd * xv) * silu_f(zz);
        }
    }
}

// ---------------- GroupNorm(1, DM) over (C,L) per sample -------------------------
__global__ void k_gn_zero() { if (threadIdx.x < 8) g_red[threadIdx.x] = 0.f; }

__global__ void k_gn_reduce() {
    int b = blockIdx.y;
    const float* p = g_o2 + (size_t)b * LL * DMm;
    float s = 0.f, s2 = 0.f;
    for (int i = blockIdx.x * blockDim.x + threadIdx.x; i < LL * DMm;
         i += gridDim.x * blockDim.x) {
        float v = p[i];
        s += v; s2 += v * v;
    }
    __shared__ float sh0[256], sh1[256];
    sh0[threadIdx.x] = s; sh1[threadIdx.x] = s2;
    __syncthreads();
    for (int o = 128; o > 0; o >>= 1) {
        if (threadIdx.x < o) {
            sh0[threadIdx.x] += sh0[threadIdx.x + o];
            sh1[threadIdx.x] += sh1[threadIdx.x + o];
        }
        __syncthreads();
    }
    if (threadIdx.x == 0) {
        atomicAdd(&g_red[b], sh0[0]);
        atomicAdd(&g_red[4 + b], sh1[0]);
    }
}

__global__ void k_gn_finalize() {
    int b = threadIdx.x;
    if (b < 4) {
        float nInv = 1.f / (float)(LL * DMm);
        float mu = g_red[b] * nInv;
        float var = g_red[4 + b] * nInv - mu * mu;
        g_stat[b] = mu;
        g_stat[4 + b] = rsqrtf(var + 1e-5f);
    }
}

__global__ void k_gn_write(float* __restrict__ out,
                           const float* __restrict__ gamma,
                           const float* __restrict__ beta) {
    __shared__ float t[32][33];
    int b = blockIdx.z;
    float mu = g_stat[b], rs = g_stat[4 + b];
    int l0 = blockIdx.x * 32, c0 = blockIdx.y * 32;
    int tx = threadIdx.x, ty = threadIdx.y;            // block (32,8)
#pragma unroll
    for (int i = 0; i < 32; i += 8)
        t[ty + i][tx] = g_o2[((size_t)b * LL + l0 + ty + i) * DMm + c0 + tx];
    __syncthreads();
#pragma unroll
    for (int i = 0; i < 32; i += 8) {
        int c = c0 + ty + i;
        out[((size_t)b * DMm + c) * LL + l0 + tx] =
            (t[tx][ty + i] - mu) * rs * gamma[c] + beta[c];
    }
}

// ---------------- host launcher ---------------------------------------------------
extern "C" void kernel_launch(void* const* d_in, const int* in_sizes, int n_in,
                              void* d_out, int out_size) {
    const float* x         = (const float*)d_in[0];
    const float* in_proj_w = (const float*)d_in[1];
    const float* conv1d_w  = (const float*)d_in[2];
    const float* conv1d_b  = (const float*)d_in[3];
    const float* x_proj_w  = (const float*)d_in[4];
    const float* dt_proj_w = (const float*)d_in[5];
    const float* dt_proj_b = (const float*)d_in[6];
    const float* A_log     = (const float*)d_in[7];
    const float* Dp        = (const float*)d_in[8];
    const float* out_proj_w= (const float*)d_in[9];
    const float* conv_w    = (const float*)d_in[10];
    const float* conv_b    = (const float*)d_in[11];
    const float* gamma     = (const float*)d_in[12];
    const float* beta      = (const float*)d_in[13];
    float* out = (float*)d_out;

    const int SM_BIG   = NSTG * (128 + 128) * BKP * 4;  // 61440
    const int SM_SMALL = NSTG * (64 + 64) * BKP * 4;    // 30720

    static float *p_xT = nullptr, *p_xz, *p_xc, *p_xdbl, *p_dt, *p_y, *p_o1, *p_o2;
    if (!p_xT) {
        cudaGetSymbolAddress((void**)&p_xT,   g_xT);
        cudaGetSymbolAddress((void**)&p_xz,   g_xz);
        cudaGetSymbolAddress((void**)&p_xc,   g_xc);
        cudaGetSymbolAddress((void**)&p_xdbl, g_xdbl);
        cudaGetSymbolAddress((void**)&p_dt,   g_dt);
        cudaGetSymbolAddress((void**)&p_y,    g_y);
        cudaGetSymbolAddress((void**)&p_o1,   g_o1);
        cudaGetSymbolAddress((void**)&p_o2,   g_o2);
        cudaFuncSetAttribute((const void*)k_gemm_ca<128,128,2,4,0>,
                             cudaFuncAttributeMaxDynamicSharedMemorySize, SM_BIG);
        cudaFuncSetAttribute((const void*)k_gemm_ca<128,128,2,4,1>,
                             cudaFuncAttributeMaxDynamicSharedMemorySize, SM_BIG);
        cudaFuncSetAttribute((const void*)k_gemm_ca<128,128,2,4,2>,
                             cudaFuncAttributeMaxDynamicSharedMemorySize, SM_BIG);
        cudaFuncSetAttribute((const void*)k_gemm_ca<64,64,4,2,0>,
                             cudaFuncAttributeMaxDynamicSharedMemorySize, SM_SMALL);
    }

    dim3 tb(32, 8);
    // 0. transpose x -> xT [m, DM]
    k_transpose_x<<<dim3(LL / 32, DMm / 32, BB), tb>>>(x);

    // 1. xz = xT @ in_proj_w^T   [m, 2048]
    k_gemm_ca<128,128,2,4,0><<<dim3(2 * DIi / 128, MT / 128), 256, SM_BIG>>>(
        p_xT, DMm, in_proj_w, p_xz, 2 * DIi, DMm, nullptr);

    // 2. causal depthwise conv1d + silu -> xc
    k_conv1d_silu<<<(MT * DIi) / 256, 256>>>(conv1d_w, conv1d_b);

    // 3. x_dbl = xc @ x_proj_w^T  [m, 64]
    k_gemm_ca<64,64,4,2,0><<<dim3(1, MT / 64), 256, SM_SMALL>>>(
        p_xc, DIi, x_proj_w, p_xdbl, 64, DIi, nullptr);

    // 4. dt = softplus(x_dbl[:, :32] @ dt_proj_w^T + b)  [m, 1024]
    k_gemm_ca<128,128,2,4,1><<<dim3(DIi / 128, MT / 128), 256, SM_BIG>>>(
        p_xdbl, 64, dt_proj_w, p_dt, DIi, DTRr, dt_proj_b);

    // 5. chunked selective scan
    k_scanA<<<(CH * BB * DIi * DSs) / 256, 256>>>(A_log);
    k_scanC<<<(BB * DIi * DSs) / 256, 256>>>();
    k_scanB<<<(CH * BB * DIi * DSs) / 256, 256>>>(A_log, Dp);

    // 6. o1 = y @ out_proj_w^T  [m, 512]
    k_gemm_ca<128,128,2,4,0><<<dim3(DMm / 128, MT / 128), 256, SM_BIG>>>(
        p_y, DIi, out_proj_w, p_o1, DMm, DIi, nullptr);

    // 7. o2 = gelu(o1 @ conv_w^T + conv_b)  [m, 512]
    k_gemm_ca<128,128,2,4,2><<<dim3(DMm / 128, MT / 128), 256, SM_BIG>>>(
        p_o1, DMm, conv_w, p_o2, DMm, DMm, conv_b);

    // 8. GroupNorm stats + normalize + affine + transpose to [B, DM, L]
    k_gn_zero<<<1, 32>>>();
    k_gn_reduce<<<dim3(128, BB), 256>>>();
    k_gn_finalize<<<1, 32>>>();
    k_gn_write<<<dim3(LL / 32, DMm / 32, BB), tb>>>(out, gamma, beta);
}

// round 5
// speedup vs baseline: 3.2937x; 1.0153x over previous
#include <cuda_runtime.h>
#include <math.h>
#include <stdint.h>

#define BB  4
#define LL  4096
#define DMm 512
#define DIi 1024
#define DSs 16
#define DCc 4
#define DTRr 32
#define MT  (BB*LL)   /* 16384 rows */
#define CH  16        /* scan chunks */
#define CS  (LL/CH)   /* 256 steps per chunk */

// ---------------- scratch (static device globals; no runtime alloc) -------------
__device__ float g_xT  [MT * DMm];
__device__ float g_xz  [MT * 2 * DIi];
__device__ float g_xc  [MT * DIi];
__device__ float g_xdbl[MT * 64];
__device__ float g_dt  [MT * DIi];
__device__ float g_y   [MT * DIi];
__device__ float g_o1  [MT * DMm];
__device__ float g_o2  [MT * DMm];
__device__ float g_S   [CH * BB * DIi * DSs];
__device__ float g_P   [CH * BB * DIi * DSs];
__device__ float g_hi  [CH * BB * DIi * DSs];
__device__ float g_red [8];
__device__ float g_stat[8];
// rna-rounded tf32 weight copies (so raw-bit mma feed is exact)
__device__ float g_w1  [2 * DIi * DMm];
__device__ float g_wxp [64 * DIi];
__device__ float g_wdt [DIi * DTRr];
__device__ float g_wout[DMm * DIi];
__device__ float g_wcv [DMm * DMm];

// ---------------- helpers --------------------------------------------------------
__device__ __forceinline__ float softplus_f(float x) {
    return x > 20.f ? x : log1pf(__expf(x));
}
__device__ __forceinline__ float gelu_f(float x) {
    return 0.5f * x * (1.f + erff(x * 0.70710678118654752f));
}
__device__ __forceinline__ float silu_f(float x) {
    return x / (1.f + __expf(-x));
}
__device__ __forceinline__ float rna_tf32(float f) {
    unsigned r;
    asm("cvt.rna.tf32.f32 %0, %1;" : "=r"(r) : "f"(f));
    return __uint_as_float(r);
}
__device__ __forceinline__ void mma_tf32(float* d, const unsigned* a, const unsigned* b) {
    asm volatile(
        "mma.sync.aligned.m16n8k8.row.col.f32.tf32.tf32.f32 "
        "{%0,%1,%2,%3}, {%4,%5,%6,%7}, {%8,%9}, {%0,%1,%2,%3};"
        : "+f"(d[0]), "+f"(d[1]), "+f"(d[2]), "+f"(d[3])
        : "r"(a[0]), "r"(a[1]), "r"(a[2]), "r"(a[3]), "r"(b[0]), "r"(b[1]));
}
__device__ __forceinline__ void cp16(float* dst_smem, const float* src) {
    unsigned d = (unsigned)__cvta_generic_to_shared(dst_smem);
    asm volatile("cp.async.cg.shared.global [%0], [%1], 16;\n" :: "r"(d), "l"(src));
}
__device__ __forceinline__ void cp_commit() { asm volatile("cp.async.commit_group;\n"); }
template <int N>
__device__ __forceinline__ void cp_wait() { asm volatile("cp.async.wait_group %0;\n" :: "n"(N)); }

// ---------------- weight rounding copy -------------------------------------------
__global__ void k_round(const float* __restrict__ s, float* __restrict__ d, int n) {
    int i = blockIdx.x * blockDim.x + threadIdx.x;
    if (i < n) d[i] = rna_tf32(s[i]);
}

// ---------------- 0. transpose x [B,DM,L] -> xT [m, DM] (rna-rounded) ------------
__global__ void k_transpose_x(const float* __restrict__ x) {
    __shared__ float t[32][33];
    int b  = blockIdx.z;
    int l0 = blockIdx.x * 32, d0 = blockIdx.y * 32;
    int tx = threadIdx.x, ty = threadIdx.y;            // block (32,8)
#pragma unroll
    for (int i = 0; i < 32; i += 8)
        t[ty + i][tx] = x[((size_t)b * DMm + d0 + ty + i) * LL + l0 + tx];
    __syncthreads();
#pragma unroll
    for (int i = 0; i < 32; i += 8)
        g_xT[((size_t)b * LL + l0 + ty + i) * DMm + d0 + tx] = rna_tf32(t[tx][ty + i]);
}

// ---------- tf32 GEMM, cp.async 3-stage pipeline: C = A(m,k) * W(n,k)^T ----------
// Inputs MUST be pre-rounded to tf32 (rna); fragments feed raw f32 bits to mma.
// EPI: 0 none, 1 +bias softplus, 2 +bias exact GELU. RND: rna-round the output.
#define BKg  16
#define BKP  20
#define NSTG 3

template <int BM, int BN, int WM, int WN, int EPI, bool RND>
__global__ void __launch_bounds__(256, 2)
k_gemm_ca(const float* __restrict__ A, int lda,
          const float* __restrict__ W,
          float* __restrict__ C, int N, int K,
          const float* __restrict__ bias) {
    constexpr int WTM = BM / WM, WTN = BN / WN;
    constexpr int MTl = WTM / 16, NTl = WTN / 8;
    constexpr int CA = BM / 64, CB = BN / 64;   // 16B chunks per thread per stage

    extern __shared__ float sm[];
    float* As = sm;                         // [NSTG][BM][BKP]
    float* Bs = sm + NSTG * BM * BKP;       // [NSTG][BN][BKP]

    int tid = threadIdx.x;
    int warp = tid >> 5, lane = tid & 31;
    int wm = warp / WN, wn = warp % WN;
    int g = lane >> 2, t = lane & 3;
    int m0 = blockIdx.y * BM, n0 = blockIdx.x * BN;

    float acc[MTl][NTl][4];
#pragma unroll
    for (int i = 0; i < MTl; i++)
#pragma unroll
        for (int j = 0; j < NTl; j++)
#pragma unroll
            for (int r = 0; r < 4; r++) acc[i][j][r] = 0.f;

    const int nIter = K / BKg;

    auto issue = [&](int s, int kt) {
        int k0 = kt * BKg;
#pragma unroll
        for (int i = 0; i < CA; i++) {
            int ch = tid + 256 * i;
            int r = ch >> 2, cc = (ch & 3) * 4;
            cp16(&As[(s * BM + r) * BKP + cc], A + (size_t)(m0 + r) * lda + k0 + cc);
        }
#pragma unroll
        for (int i = 0; i < CB; i++) {
            int ch = tid + 256 * i;
            int r = ch >> 2, cc = (ch & 3) * 4;
            cp16(&Bs[(s * BN + r) * BKP + cc], W + (size_t)(n0 + r) * K + k0 + cc);
        }
    };

#pragma unroll
    for (int s = 0; s < NSTG - 1; s++) {
        if (s < nIter) issue(s, s);
        cp_commit();
    }

    for (int it = 0; it < nIter; it++) {
        cp_wait<NSTG - 2>();
        __syncthreads();
        int nxt = it + NSTG - 1;
        if (nxt < nIter) issue(nxt % NSTG, nxt);
        cp_commit();

        const float* as = As + (it % NSTG) * BM * BKP;
        const float* bs = Bs + (it % NSTG) * BN * BKP;
#pragma unroll
        for (int kk = 0; kk < 2; kk++) {
            unsigned af[MTl][4], bf[NTl][2];
#pragma unroll
            for (int i = 0; i < MTl; i++) {
                int m = wm * WTM + i * 16;
                af[i][0] = __float_as_uint(as[(m + g) * BKP + kk * 8 + t]);
                af[i][1] = __float_as_uint(as[(m + g + 8) * BKP + kk * 8 + t]);
                af[i][2] = __float_as_uint(as[(m + g) * BKP + kk * 8 + t + 4]);
                af[i][3] = __float_as_uint(as[(m + g + 8) * BKP + kk * 8 + t + 4]);
            }
#pragma unroll
            for (int j = 0; j < NTl; j++) {
                int n = wn * WTN + j * 8;
                bf[j][0] = __float_as_uint(bs[(n + g) * BKP + kk * 8 + t]);
                bf[j][1] = __float_as_uint(bs[(n + g) * BKP + kk * 8 + t + 4]);
            }
#pragma unroll
            for (int i = 0; i < MTl; i++)
#pragma unroll
                for (int j = 0; j < NTl; j++)
                    mma_tf32(acc[i][j], af[i], bf[j]);
        }
    }

    // epilogue: c0:(g,2t) c1:(g,2t+1) c2:(g+8,2t) c3:(g+8,2t+1)
#pragma unroll
    for (int i = 0; i < MTl; i++) {
#pragma unroll
        for (int j = 0; j < NTl; j++) {
            int m = m0 + wm * WTM + i * 16 + g;
            int n = n0 + wn * WTN + j * 8 + 2 * t;
            float b0 = 0.f, b1 = 0.f;
            if (EPI != 0) { b0 = bias[n]; b1 = bias[n + 1]; }
            float v0 = acc[i][j][0], v1 = acc[i][j][1];
            float v2 = acc[i][j][2], v3 = acc[i][j][3];
            if (EPI == 1) { v0 = softplus_f(v0 + b0); v1 = softplus_f(v1 + b1);
                            v2 = softplus_f(v2 + b0); v3 = softplus_f(v3 + b1); }
            if (EPI == 2) { v0 = gelu_f(v0 + b0); v1 = gelu_f(v1 + b1);
                            v2 = gelu_f(v2 + b0); v3 = gelu_f(v3 + b1); }
            if (RND) { v0 = rna_tf32(v0); v1 = rna_tf32(v1);
                       v2 = rna_tf32(v2); v3 = rna_tf32(v3); }
            *(float2*)&C[(size_t)m * N + n]       = make_float2(v0, v1);
            *(float2*)&C[(size_t)(m + 8) * N + n] = make_float2(v2, v3);
        }
    }
}

// ---------------- 2. causal depthwise conv1d + silu (rna-rounded out) ------------
__global__ void k_conv1d_silu(const float* __restrict__ w, const float* __restrict__ bias) {
    int idx = blockIdx.x * blockDim.x + threadIdx.x;   // over MT*DI
    int d = idx & (DIi - 1);
    int m = idx >> 10;
    int l = m & (LL - 1);
    float acc = bias[d];
#pragma unroll
    for (int k = 0; k < DCc; k++) {
        int ls = l - (DCc - 1) + k;
        if (ls >= 0)
            acc = fmaf(w[d * DCc + k], g_xz[(size_t)(m - (DCc - 1) + k) * 2 * DIi + d], acc);
    }
    g_xc[idx] = rna_tf32(silu_f(acc));
}

// ---------------- 5a. chunked scan pass A ----------------------------------------
__global__ void k_scanA(const float* __restrict__ A_log) {
    int t = blockIdx.x * blockDim.x + threadIdx.x;  // CH*4096*16 threads
    int n = t & 15;
    int chain = (t >> 4) & 4095;          // b*1024 + d
    int c = t >> 16;
    int b = chain >> 10;
    int d = chain & (DIi - 1);

    float a = -__expf(A_log[d * DSs + n]);
    int mb = b * LL + c * CS;

    const float* dt_p = g_dt   + (size_t)mb * DIi + d;
    const float* xc_p = g_xc   + (size_t)mb * DIi + d;
    const float* bd_p = g_xdbl + (size_t)mb * 64;

    float h = 0.f, sdt = 0.f;
    for (int l = 0; l < CS; l++) {
        float dt = dt_p[(size_t)l * DIi];
        float xv = xc_p[(size_t)l * DIi];
        float bn = bd_p[l * 64 + DTRr + n];
        h = fmaf(__expf(dt * a), h, dt * xv * bn);
        sdt += dt;
    }
    int o = (c * 4096 + chain) * DSs + n;
    g_S[o] = h;
    g_P[o] = __expf(a * sdt);
}

// ---------------- 5b. combine chunk states ---------------------------------------
__global__ void k_scanC() {
    int t = blockIdx.x * blockDim.x + threadIdx.x;  // 65536 threads
    float h = 0.f;
#pragma unroll
    for (int c = 0; c < CH; c++) {
        int o = (c * 4096 << 4) + t;
        g_hi[o] = h;
        h = g_S[o] + g_P[o] * h;
    }
}

// ---------------- 5c. chunked scan pass B (rna-rounded y) ------------------------
__global__ void k_scanB(const float* __restrict__ A_log, const float* __restrict__ Dp) {
    int t = blockIdx.x * blockDim.x + threadIdx.x;
    int n = t & 15;
    int chain = (t >> 4) & 4095;
    int c = t >> 16;
    int b = chain >> 10;
    int d = chain & (DIi - 1);

    float a  = -__expf(A_log[d * DSs + n]);
    float Dd = Dp[d];
    float h  = g_hi[(c * 4096 + chain) * DSs + n];
    int mb = b * LL + c * CS;

    const float* dt_p = g_dt   + (size_t)mb * DIi + d;
    const float* xc_p = g_xc   + (size_t)mb * DIi + d;
    const float* bd_p = g_xdbl + (size_t)mb * 64;
    const float* z_p  = g_xz   + (size_t)mb * 2 * DIi + DIi + d;
    float*       y_p  = g_y    + (size_t)mb * DIi + d;

    for (int l = 0; l < CS; l++) {
        float dt = dt_p[(size_t)l * DIi];
        float xv = xc_p[(size_t)l * DIi];
        float bn = bd_p[l * 64 + DTRr + n];
        float cn = bd_p[l * 64 + DTRr + DSs + n];
        h = fmaf(__expf(dt * a), h, dt * xv * bn);
        float p = h * cn;
        p += __shfl_xor_sync(0xffffffffu, p, 8);
        p += __shfl_xor_sync(0xffffffffu, p, 4);
        p += __shfl_xor_sync(0xffffffffu, p, 2);
        p += __shfl_xor_sync(0xffffffffu, p, 1);
        if (n == 0) {
            float zz = z_p[(size_t)l * 2 * DIi];
            y_p[(size_t)l * DIi] = rna_tf32((p + Dd * xv) * silu_f(zz));
        }
    }
}

// ---------------- GroupNorm(1, DM) ------------------------------------------------
__global__ void k_gn_zero() { if (threadIdx.x < 8) g_red[threadIdx.x] = 0.f; }

__global__ void k_gn_reduce() {
    int b = blockIdx.y;
    const float* p = g_o2 + (size_t)b * LL * DMm;
    float s = 0.f, s2 = 0.f;
    for (int i = blockIdx.x * blockDim.x + threadIdx.x; i < LL * DMm;
         i += gridDim.x * blockDim.x) {
        float v = p[i];
        s += v; s2 += v * v;
    }
    __shared__ float sh0[256], sh1[256];
    sh0[threadIdx.x] = s; sh1[threadIdx.x] = s2;
    __syncthreads();
    for (int o = 128; o > 0; o >>= 1) {
        if (threadIdx.x < o) {
            sh0[threadIdx.x] += sh0[threadIdx.x + o];
            sh1[threadIdx.x] += sh1[threadIdx.x + o];
        }
        __syncthreads();
    }
    if (threadIdx.x == 0) {
        atomicAdd(&g_red[b], sh0[0]);
        atomicAdd(&g_red[4 + b], sh1[0]);
    }
}

__global__ void k_gn_finalize() {
    int b = threadIdx.x;
    if (b < 4) {
        float nInv = 1.f / (float)(LL * DMm);
        float mu = g_red[b] * nInv;
        float var = g_red[4 + b] * nInv - mu * mu;
        g_stat[b] = mu;
        g_stat[4 + b] = rsqrtf(var + 1e-5f);
    }
}

__global__ void k_gn_write(float* __restrict__ out,
                           const float* __restrict__ gamma,
                           const float* __restrict__ beta) {
    __shared__ float t[32][33];
    int b = blockIdx.z;
    float mu = g_stat[b], rs = g_stat[4 + b];
    int l0 = blockIdx.x * 32, c0 = blockIdx.y * 32;
    int tx = threadIdx.x, ty = threadIdx.y;
#pragma unroll
    for (int i = 0; i < 32; i += 8)
        t[ty + i][tx] = g_o2[((size_t)b * LL + l0 + ty + i) * DMm + c0 + tx];
    __syncthreads();
#pragma unroll
    for (int i = 0; i < 32; i += 8) {
        int c = c0 + ty + i;
        out[((size_t)b * DMm + c) * LL + l0 + tx] =
            (t[tx][ty + i] - mu) * rs * gamma[c] + beta[c];
    }
}

// ---------------- host launcher ---------------------------------------------------
extern "C" void kernel_launch(void* const* d_in, const int* in_sizes, int n_in,
                              void* d_out, int out_size) {
    const float* x         = (const float*)d_in[0];
    const float* in_proj_w = (const float*)d_in[1];
    const float* conv1d_w  = (const float*)d_in[2];
    const float* conv1d_b  = (const float*)d_in[3];
    const float* x_proj_w  = (const float*)d_in[4];
    const float* dt_proj_w = (const float*)d_in[5];
    const float* dt_proj_b = (const float*)d_in[6];
    const float* A_log     = (const float*)d_in[7];
    const float* Dp        = (const float*)d_in[8];
    const float* out_proj_w= (const float*)d_in[9];
    const float* conv_w    = (const float*)d_in[10];
    const float* conv_b    = (const float*)d_in[11];
    const float* gamma     = (const float*)d_in[12];
    const float* beta      = (const float*)d_in[13];
    float* out = (float*)d_out;

    const int SM_BIG   = NSTG * (128 + 128) * BKP * 4;  // 61440
    const int SM_SMALL = NSTG * (64 + 64) * BKP * 4;    // 30720

    static float *p_xT = nullptr, *p_xz, *p_xc, *p_xdbl, *p_dt, *p_y, *p_o1, *p_o2;
    static float *p_w1, *p_wxp, *p_wdt, *p_wout, *p_wcv;
    if (!p_xT) {
        cudaGetSymbolAddress((void**)&p_xT,   g_xT);
        cudaGetSymbolAddress((void**)&p_xz,   g_xz);
        cudaGetSymbolAddress((void**)&p_xc,   g_xc);
        cudaGetSymbolAddress((void**)&p_xdbl, g_xdbl);
        cudaGetSymbolAddress((void**)&p_dt,   g_dt);
        cudaGetSymbolAddress((void**)&p_y,    g_y);
        cudaGetSymbolAddress((void**)&p_o1,   g_o1);
        cudaGetSymbolAddress((void**)&p_o2,   g_o2);
        cudaGetSymbolAddress((void**)&p_w1,   g_w1);
        cudaGetSymbolAddress((void**)&p_wxp,  g_wxp);
        cudaGetSymbolAddress((void**)&p_wdt,  g_wdt);
        cudaGetSymbolAddress((void**)&p_wout, g_wout);
        cudaGetSymbolAddress((void**)&p_wcv,  g_wcv);
        cudaFuncSetAttribute((const void*)k_gemm_ca<128,128,2,4,0,false>,
                             cudaFuncAttributeMaxDynamicSharedMemorySize, SM_BIG);
        cudaFuncSetAttribute((const void*)k_gemm_ca<128,128,2,4,0,true>,
                             cudaFuncAttributeMaxDynamicSharedMemorySize, SM_BIG);
        cudaFuncSetAttribute((const void*)k_gemm_ca<128,128,2,4,1,false>,
                             cudaFuncAttributeMaxDynamicSharedMemorySize, SM_BIG);
        cudaFuncSetAttribute((const void*)k_gemm_ca<128,128,2,4,2,false>,
                             cudaFuncAttributeMaxDynamicSharedMemorySize, SM_BIG);
        cudaFuncSetAttribute((const void*)k_gemm_ca<64,64,4,2,0,true>,
                             cudaFuncAttributeMaxDynamicSharedMemorySize, SM_SMALL);
    }

    dim3 tb(32, 8);
    // weights -> rna-rounded tf32 copies (cheap; keeps mma raw-bit feed exact)
    k_round<<<(2 * DIi * DMm) / 256, 256>>>(in_proj_w, p_w1, 2 * DIi * DMm);
    k_round<<<(64 * DIi) / 256, 256>>>(x_proj_w, p_wxp, 64 * DIi);
    k_round<<<(DIi * DTRr) / 256, 256>>>(dt_proj_w, p_wdt, DIi * DTRr);
    k_round<<<(DMm * DIi) / 256, 256>>>(out_proj_w, p_wout, DMm * DIi);
    k_round<<<(DMm * DMm) / 256, 256>>>(conv_w, p_wcv, DMm * DMm);

    // 0. transpose x -> xT [m, DM] (rounded)
    k_transpose_x<<<dim3(LL / 32, DMm / 32, BB), tb>>>(x);

    // 1. xz = xT @ in_proj_w^T   [m, 2048]  (no output rounding needed)
    k_gemm_ca<128,128,2,4,0,false><<<dim3(2 * DIi / 128, MT / 128), 256, SM_BIG>>>(
        p_xT, DMm, p_w1, p_xz, 2 * DIi, DMm, nullptr);

    // 2. causal depthwise conv1d + silu -> xc (rounded: feeds x_proj GEMM)
    k_conv1d_silu<<<(MT * DIi) / 256, 256>>>(conv1d_w, conv1d_b);

    // 3. x_dbl = xc @ x_proj_w^T  [m, 64] (rounded: feeds dt GEMM)
    k_gemm_ca<64,64,4,2,0,true><<<dim3(1, MT / 64), 256, SM_SMALL>>>(
        p_xc, DIi, p_wxp, p_xdbl, 64, DIi, nullptr);

    // 4. dt = softplus(x_dbl[:, :32] @ dt_proj_w^T + b)  [m, 1024]
    k_gemm_ca<128,128,2,4,1,false><<<dim3(DIi / 128, MT / 128), 256, SM_BIG>>>(
        p_xdbl, 64, p_wdt, p_dt, DIi, DTRr, dt_proj_b);

    // 5. chunked selective scan (y rounded: feeds out_proj GEMM)
    k_scanA<<<(CH * BB * DIi * DSs) / 256, 256>>>(A_log);
    k_scanC<<<(BB * DIi * DSs) / 256, 256>>>();
    k_scanB<<<(CH * BB * DIi * DSs) / 256, 256>>>(A_log, Dp);

    // 6. o1 = y @ out_proj_w^T  [m, 512] (rounded: feeds conv GEMM)
    k_gemm_ca<128,128,2,4,0,true><<<dim3(DMm / 128, MT / 128), 256, SM_BIG>>>(
        p_y, DIi, p_wout, p_o1, DMm, DIi, nullptr);

    // 7. o2 = gelu(o1 @ conv_w^T + conv_b)  [m, 512]
    k_gemm_ca<128,128,2,4,2,false><<<dim3(DMm / 128, MT / 128), 256, SM_BIG>>>(
        p_o1, DMm, p_wcv, p_o2, DMm, DMm, conv_b);

    // 8. GroupNorm
    k_gn_zero<<<1, 32>>>();
    k_gn_reduce<<<dim3(128, BB), 256>>>();
    k_gn_finalize<<<1, 32>>>();
    k_gn_write<<<dim3(LL / 32, DMm / 32, BB), tb>>>(out, gamma, beta);
}

// round 6
// speedup vs baseline: 3.3910x; 1.0296x over previous
#include <cuda_runtime.h>
#include <math.h>
#include <stdint.h>

#define BB  4
#define LL  4096
#define DMm 512
#define DIi 1024
#define DSs 16
#define DCc 4
#define DTRr 32
#define MT  (BB*LL)   /* 16384 rows */
#define CH  16        /* scan chunks */
#define CS  (LL/CH)   /* 256 steps per chunk */

// ---------------- scratch (static device globals; no runtime alloc) -------------
__device__ float g_xT  [MT * DMm];
__device__ float g_xz  [MT * 2 * DIi];
__device__ float g_xc  [MT * DIi];
__device__ float g_xdbl[MT * 64];
__device__ float g_dt  [MT * DIi];
__device__ float g_y   [MT * DIi];
__device__ float g_o1  [MT * DMm];
__device__ float g_o2  [MT * DMm];
__device__ float g_S   [CH * BB * DIi * DSs];
__device__ float g_P   [CH * BB * DIi * DSs];
__device__ float g_hi  [CH * BB * DIi * DSs];
__device__ float g_red [8];
__device__ float g_stat[8];
// rna-rounded tf32 weight copies (so raw-bit mma feed is exact)
__device__ float g_w1  [2 * DIi * DMm];
__device__ float g_wxp [64 * DIi];
__device__ float g_wdt [DIi * DTRr];
__device__ float g_wout[DMm * DIi];
__device__ float g_wcv [DMm * DMm];

// ---------------- helpers --------------------------------------------------------
__device__ __forceinline__ float softplus_f(float x) {
    return x > 20.f ? x : log1pf(__expf(x));
}
__device__ __forceinline__ float gelu_f(float x) {
    return 0.5f * x * (1.f + erff(x * 0.70710678118654752f));
}
__device__ __forceinline__ float silu_f(float x) {
    return x / (1.f + __expf(-x));
}
__device__ __forceinline__ float rna_tf32(float f) {
    unsigned r;
    asm("cvt.rna.tf32.f32 %0, %1;" : "=r"(r) : "f"(f));
    return __uint_as_float(r);
}
__device__ __forceinline__ void mma_tf32(float* d, const unsigned* a, const unsigned* b) {
    asm volatile(
        "mma.sync.aligned.m16n8k8.row.col.f32.tf32.tf32.f32 "
        "{%0,%1,%2,%3}, {%4,%5,%6,%7}, {%8,%9}, {%0,%1,%2,%3};"
        : "+f"(d[0]), "+f"(d[1]), "+f"(d[2]), "+f"(d[3])
        : "r"(a[0]), "r"(a[1]), "r"(a[2]), "r"(a[3]), "r"(b[0]), "r"(b[1]));
}
__device__ __forceinline__ void cp16(float* dst_smem, const float* src) {
    unsigned d = (unsigned)__cvta_generic_to_shared(dst_smem);
    asm volatile("cp.async.cg.shared.global [%0], [%1], 16;\n" :: "r"(d), "l"(src));
}
__device__ __forceinline__ void cp_commit() { asm volatile("cp.async.commit_group;\n"); }
template <int N>
__device__ __forceinline__ void cp_wait() { asm volatile("cp.async.wait_group %0;\n" :: "n"(N)); }

// ---------------- weight rounding copy -------------------------------------------
__global__ void k_round(const float* __restrict__ s, float* __restrict__ d, int n) {
    int i = blockIdx.x * blockDim.x + threadIdx.x;
    if (i < n) d[i] = rna_tf32(s[i]);
}

// ---------------- 0. transpose x [B,DM,L] -> xT [m, DM] (rna-rounded) ------------
__global__ void k_transpose_x(const float* __restrict__ x) {
    __shared__ float t[32][33];
    int b  = blockIdx.z;
    int l0 = blockIdx.x * 32, d0 = blockIdx.y * 32;
    int tx = threadIdx.x, ty = threadIdx.y;            // block (32,8)
#pragma unroll
    for (int i = 0; i < 32; i += 8)
        t[ty + i][tx] = x[((size_t)b * DMm + d0 + ty + i) * LL + l0 + tx];
    __syncthreads();
#pragma unroll
    for (int i = 0; i < 32; i += 8)
        g_xT[((size_t)b * LL + l0 + ty + i) * DMm + d0 + tx] = rna_tf32(t[tx][ty + i]);
}

// ---------- tf32 GEMM, cp.async 3-stage + register-fragment double buffering -----
// Inputs MUST be pre-rounded to tf32 (rna); fragments feed raw f32 bits to mma.
// EPI: 0 none, 1 +bias softplus, 2 +bias exact GELU. RND: rna-round the output.
#define BKg  16
#define BKP  20
#define NSTG 3

template <int BM, int BN, int WM, int WN, int EPI, bool RND>
__global__ void __launch_bounds__(256, 2)
k_gemm_ca(const float* __restrict__ A, int lda,
          const float* __restrict__ W,
          float* __restrict__ C, int N, int K,
          const float* __restrict__ bias) {
    constexpr int WTM = BM / WM, WTN = BN / WN;
    constexpr int MTl = WTM / 16, NTl = WTN / 8;
    constexpr int CA = BM / 64, CB = BN / 64;   // 16B chunks per thread per stage

    extern __shared__ float sm[];
    float* As = sm;                         // [NSTG][BM][BKP]
    float* Bs = sm + NSTG * BM * BKP;       // [NSTG][BN][BKP]

    int tid = threadIdx.x;
    int warp = tid >> 5, lane = tid & 31;
    int wm = warp / WN, wn = warp % WN;
    int g = lane >> 2, t = lane & 3;
    int m0 = blockIdx.y * BM, n0 = blockIdx.x * BN;

    // staging: per-thread base pointers / smem offsets
    int srow = tid >> 2, scol = (tid & 3) * 4;
    const float* Ag = A + (size_t)(m0 + srow) * lda + scol;
    const float* Bg = W + (size_t)(n0 + srow) * K + scol;
    int sAo = srow * BKP + scol;
    int sBo = srow * BKP + scol;

    float acc[MTl][NTl][4];
#pragma unroll
    for (int i = 0; i < MTl; i++)
#pragma unroll
        for (int j = 0; j < NTl; j++)
#pragma unroll
            for (int r = 0; r < 4; r++) acc[i][j][r] = 0.f;

    const int nIter = K / BKg;

    auto issue = [&](int slot, int kt) {
        int k0 = kt * BKg;
#pragma unroll
        for (int i = 0; i < CA; i++)
            cp16(&As[slot * BM * BKP + sAo + i * 64 * BKP], Ag + (size_t)(64 * i) * lda + k0);
#pragma unroll
        for (int i = 0; i < CB; i++)
            cp16(&Bs[slot * BN * BKP + sBo + i * 64 * BKP], Bg + (size_t)(64 * i) * K + k0);
    };

    // prologue: stages 0,1
    issue(0, 0);
    cp_commit();
    if (1 < nIter) issue(1, 1);
    cp_commit();
    cp_wait<1>();
    __syncthreads();

    unsigned afA[MTl][4], bfA[NTl][2], afB[MTl][4], bfB[NTl][2];

    auto ldfragA = [&](const float* as, const float* bs, int kk,
                       unsigned (&af)[MTl][4], unsigned (&bf)[NTl][2]) {
#pragma unroll
        for (int i = 0; i < MTl; i++) {
            int m = wm * WTM + i * 16;
            af[i][0] = __float_as_uint(as[(m + g) * BKP + kk * 8 + t]);
            af[i][1] = __float_as_uint(as[(m + g + 8) * BKP + kk * 8 + t]);
            af[i][2] = __float_as_uint(as[(m + g) * BKP + kk * 8 + t + 4]);
            af[i][3] = __float_as_uint(as[(m + g + 8) * BKP + kk * 8 + t + 4]);
        }
#pragma unroll
        for (int j = 0; j < NTl; j++) {
            int n = wn * WTN + j * 8;
            bf[j][0] = __float_as_uint(bs[(n + g) * BKP + kk * 8 + t]);
            bf[j][1] = __float_as_uint(bs[(n + g) * BKP + kk * 8 + t + 4]);
        }
    };

    ldfragA(As, Bs, 0, afA, bfA);   // stage 0, kk=0

    for (int it = 0; it < nIter; it++) {
        const float* as = As + (it % NSTG) * BM * BKP;
        const float* bs = Bs + (it % NSTG) * BN * BKP;

        // prefetch kk=1 fragments of current stage
        ldfragA(as, bs, 1, afB, bfB);

        // issue next gmem stage (overlaps with both mma bursts)
        int nxt = it + NSTG - 1;
        if (nxt < nIter) issue(nxt % NSTG, nxt);
        cp_commit();

        // mma kk=0 (frags afA ready; hides afB LDS latency)
#pragma unroll
        for (int i = 0; i < MTl; i++)
#pragma unroll
            for (int j = 0; j < NTl; j++)
                mma_tf32(acc[i][j], afA[i], bfA[j]);

        // stage it+1 smem ready
        cp_wait<NSTG - 2>();
        __syncthreads();

        // prefetch next stage kk=0 fragments (garbage on last iter; unused)
        const float* as2 = As + ((it + 1) % NSTG) * BM * BKP;
        const float* bs2 = Bs + ((it + 1) % NSTG) * BN * BKP;
        ldfragA(as2, bs2, 0, afA, bfA);

        // mma kk=1 (hides afA LDS latency)
#pragma unroll
        for (int i = 0; i < MTl; i++)
#pragma unroll
            for (int j = 0; j < NTl; j++)
                mma_tf32(acc[i][j], afB[i], bfB[j]);
    }

    // epilogue: c0:(g,2t) c1:(g,2t+1) c2:(g+8,2t) c3:(g+8,2t+1)
#pragma unroll
    for (int i = 0; i < MTl; i++) {
#pragma unroll
        for (int j = 0; j < NTl; j++) {
            int m = m0 + wm * WTM + i * 16 + g;
            int n = n0 + wn * WTN + j * 8 + 2 * t;
            float b0 = 0.f, b1 = 0.f;
            if (EPI != 0) { b0 = bias[n]; b1 = bias[n + 1]; }
            float v0 = acc[i][j][0], v1 = acc[i][j][1];
            float v2 = acc[i][j][2], v3 = acc[i][j][3];
            if (EPI == 1) { v0 = softplus_f(v0 + b0); v1 = softplus_f(v1 + b1);
                            v2 = softplus_f(v2 + b0); v3 = softplus_f(v3 + b1); }
            if (EPI == 2) { v0 = gelu_f(v0 + b0); v1 = gelu_f(v1 + b1);
                            v2 = gelu_f(v2 + b0); v3 = gelu_f(v3 + b1); }
            if (RND) { v0 = rna_tf32(v0); v1 = rna_tf32(v1);
                       v2 = rna_tf32(v2); v3 = rna_tf32(v3); }
            *(float2*)&C[(size_t)m * N + n]       = make_float2(v0, v1);
            *(float2*)&C[(size_t)(m + 8) * N + n] = make_float2(v2, v3);
        }
    }
}

// ---------------- 2. causal depthwise conv1d + silu (rna-rounded out) ------------
__global__ void k_conv1d_silu(const float* __restrict__ w, const float* __restrict__ bias) {
    int idx = blockIdx.x * blockDim.x + threadIdx.x;   // over MT*DI
    int d = idx & (DIi - 1);
    int m = idx >> 10;
    int l = m & (LL - 1);
    float acc = bias[d];
#pragma unroll
    for (int k = 0; k < DCc; k++) {
        int ls = l - (DCc - 1) + k;
        if (ls >= 0)
            acc = fmaf(w[d * DCc + k], g_xz[(size_t)(m - (DCc - 1) + k) * 2 * DIi + d], acc);
    }
    g_xc[idx] = rna_tf32(silu_f(acc));
}

// ---------------- 5a. chunked scan pass A ----------------------------------------
__global__ void k_scanA(const float* __restrict__ A_log) {
    int t = blockIdx.x * blockDim.x + threadIdx.x;  // CH*4096*16 threads
    int n = t & 15;
    int chain = (t >> 4) & 4095;          // b*1024 + d
    int c = t >> 16;
    int b = chain >> 10;
    int d = chain & (DIi - 1);

    float a = -__expf(A_log[d * DSs + n]);
    int mb = b * LL + c * CS;

    const float* dt_p = g_dt   + (size_t)mb * DIi + d;
    const float* xc_p = g_xc   + (size_t)mb * DIi + d;
    const float* bd_p = g_xdbl + (size_t)mb * 64;

    float h = 0.f, sdt = 0.f;
    for (int l = 0; l < CS; l++) {
        float dt = dt_p[(size_t)l * DIi];
        float xv = xc_p[(size_t)l * DIi];
        float bn = bd_p[l * 64 + DTRr + n];
        h = fmaf(__expf(dt * a), h, dt * xv * bn);
        sdt += dt;
    }
    int o = (c * 4096 + chain) * DSs + n;
    g_S[o] = h;
    g_P[o] = __expf(a * sdt);
}

// ---------------- 5b. combine chunk states ---------------------------------------
__global__ void k_scanC() {
    int t = blockIdx.x * blockDim.x + threadIdx.x;  // 65536 threads
    float h = 0.f;
#pragma unroll
    for (int c = 0; c < CH; c++) {
        int o = (c * 4096 << 4) + t;
        g_hi[o] = h;
        h = g_S[o] + g_P[o] * h;
    }
}

// ---------------- 5c. chunked scan pass B (rna-rounded y) ------------------------
__global__ void k_scanB(const float* __restrict__ A_log, const float* __restrict__ Dp) {
    int t = blockIdx.x * blockDim.x + threadIdx.x;
    int n = t & 15;
    int chain = (t >> 4) & 4095;
    int c = t >> 16;
    int b = chain >> 10;
    int d = chain & (DIi - 1);

    float a  = -__expf(A_log[d * DSs + n]);
    float Dd = Dp[d];
    float h  = g_hi[(c * 4096 + chain) * DSs + n];
    int mb = b * LL + c * CS;

    const float* dt_p = g_dt   + (size_t)mb * DIi + d;
    const float* xc_p = g_xc   + (size_t)mb * DIi + d;
    const float* bd_p = g_xdbl + (size_t)mb * 64;
    const float* z_p  = g_xz   + (size_t)mb * 2 * DIi + DIi + d;
    float*       y_p  = g_y    + (size_t)mb * DIi + d;

    for (int l = 0; l < CS; l++) {
        float dt = dt_p[(size_t)l * DIi];
        float xv = xc_p[(size_t)l * DIi];
        float bn = bd_p[l * 64 + DTRr + n];
        float cn = bd_p[l * 64 + DTRr + DSs + n];
        h = fmaf(__expf(dt * a), h, dt * xv * bn);
        float p = h * cn;
        p += __shfl_xor_sync(0xffffffffu, p, 8);
        p += __shfl_xor_sync(0xffffffffu, p, 4);
        p += __shfl_xor_sync(0xffffffffu, p, 2);
        p += __shfl_xor_sync(0xffffffffu, p, 1);
        if (n == 0) {
            float zz = z_p[(size_t)l * 2 * DIi];
            y_p[(size_t)l * DIi] = rna_tf32((p + Dd * xv) * silu_f(zz));
        }
    }
}

// ---------------- GroupNorm(1, DM) ------------------------------------------------
__global__ void k_gn_zero() { if (threadIdx.x < 8) g_red[threadIdx.x] = 0.f; }

__global__ void k_gn_reduce() {
    int b = blockIdx.y;
    const float* p = g_o2 + (size_t)b * LL * DMm;
    float s = 0.f, s2 = 0.f;
    for (int i = blockIdx.x * blockDim.x + threadIdx.x; i < LL * DMm;
         i += gridDim.x * blockDim.x) {
        float v = p[i];
        s += v; s2 += v * v;
    }
    __shared__ float sh0[256], sh1[256];
    sh0[threadIdx.x] = s; sh1[threadIdx.x] = s2;
    __syncthreads();
    for (int o = 128; o > 0; o >>= 1) {
        if (threadIdx.x < o) {
            sh0[threadIdx.x] += sh0[threadIdx.x + o];
            sh1[threadIdx.x] += sh1[threadIdx.x + o];
        }
        __syncthreads();
    }
    if (threadIdx.x == 0) {
        atomicAdd(&g_red[b], sh0[0]);
        atomicAdd(&g_red[4 + b], sh1[0]);
    }
}

__global__ void k_gn_finalize() {
    int b = threadIdx.x;
    if (b < 4) {
        float nInv = 1.f / (float)(LL * DMm);
        float mu = g_red[b] * nInv;
        float var = g_red[4 + b] * nInv - mu * mu;
        g_stat[b] = mu;
        g_stat[4 + b] = rsqrtf(var + 1e-5f);
    }
}

__global__ void k_gn_write(float* __restrict__ out,
                           const float* __restrict__ gamma,
                           const float* __restrict__ beta) {
    __shared__ float t[32][33];
    int b = blockIdx.z;
    float mu = g_stat[b], rs = g_stat[4 + b];
    int l0 = blockIdx.x * 32, c0 = blockIdx.y * 32;
    int tx = threadIdx.x, ty = threadIdx.y;
#pragma unroll
    for (int i = 0; i < 32; i += 8)
        t[ty + i][tx] = g_o2[((size_t)b * LL + l0 + ty + i) * DMm + c0 + tx];
    __syncthreads();
#pragma unroll
    for (int i = 0; i < 32; i += 8) {
        int c = c0 + ty + i;
        out[((size_t)b * DMm + c) * LL + l0 + tx] =
            (t[tx][ty + i] - mu) * rs * gamma[c] + beta[c];
    }
}

// ---------------- host launcher ---------------------------------------------------
extern "C" void kernel_launch(void* const* d_in, const int* in_sizes, int n_in,
                              void* d_out, int out_size) {
    const float* x         = (const float*)d_in[0];
    const float* in_proj_w = (const float*)d_in[1];
    const float* conv1d_w  = (const float*)d_in[2];
    const float* conv1d_b  = (const float*)d_in[3];
    const float* x_proj_w  = (const float*)d_in[4];
    const float* dt_proj_w = (const float*)d_in[5];
    const float* dt_proj_b = (const float*)d_in[6];
    const float* A_log     = (const float*)d_in[7];
    const float* Dp        = (const float*)d_in[8];
    const float* out_proj_w= (const float*)d_in[9];
    const float* conv_w    = (const float*)d_in[10];
    const float* conv_b    = (const float*)d_in[11];
    const float* gamma     = (const float*)d_in[12];
    const float* beta      = (const float*)d_in[13];
    float* out = (float*)d_out;

    const int SM_BIG   = NSTG * (128 + 128) * BKP * 4;  // 61440
    const int SM_SMALL = NSTG * (64 + 64) * BKP * 4;    // 30720

    static float *p_xT = nullptr, *p_xz, *p_xc, *p_xdbl, *p_dt, *p_y, *p_o1, *p_o2;
    static float *p_w1, *p_wxp, *p_wdt, *p_wout, *p_wcv;
    if (!p_xT) {
        cudaGetSymbolAddress((void**)&p_xT,   g_xT);
        cudaGetSymbolAddress((void**)&p_xz,   g_xz);
        cudaGetSymbolAddress((void**)&p_xc,   g_xc);
        cudaGetSymbolAddress((void**)&p_xdbl, g_xdbl);
        cudaGetSymbolAddress((void**)&p_dt,   g_dt);
        cudaGetSymbolAddress((void**)&p_y,    g_y);
        cudaGetSymbolAddress((void**)&p_o1,   g_o1);
        cudaGetSymbolAddress((void**)&p_o2,   g_o2);
        cudaGetSymbolAddress((void**)&p_w1,   g_w1);
        cudaGetSymbolAddress((void**)&p_wxp,  g_wxp);
        cudaGetSymbolAddress((void**)&p_wdt,  g_wdt);
        cudaGetSymbolAddress((void**)&p_wout, g_wout);
        cudaGetSymbolAddress((void**)&p_wcv,  g_wcv);
        cudaFuncSetAttribute((const void*)k_gemm_ca<128,128,2,4,0,false>,
                             cudaFuncAttributeMaxDynamicSharedMemorySize, SM_BIG);
        cudaFuncSetAttribute((const void*)k_gemm_ca<128,128,2,4,0,true>,
                             cudaFuncAttributeMaxDynamicSharedMemorySize, SM_BIG);
        cudaFuncSetAttribute((const void*)k_gemm_ca<128,128,2,4,1,false>,
                             cudaFuncAttributeMaxDynamicSharedMemorySize, SM_BIG);
        cudaFuncSetAttribute((const void*)k_gemm_ca<128,128,2,4,2,false>,
                             cudaFuncAttributeMaxDynamicSharedMemorySize, SM_BIG);
        cudaFuncSetAttribute((const void*)k_gemm_ca<64,64,4,2,0,true>,
                             cudaFuncAttributeMaxDynamicSharedMemorySize, SM_SMALL);
    }

    dim3 tb(32, 8);
    // weights -> rna-rounded tf32 copies
    k_round<<<(2 * DIi * DMm) / 256, 256>>>(in_proj_w, p_w1, 2 * DIi * DMm);
    k_round<<<(64 * DIi) / 256, 256>>>(x_proj_w, p_wxp, 64 * DIi);
    k_round<<<(DIi * DTRr) / 256, 256>>>(dt_proj_w, p_wdt, DIi * DTRr);
    k_round<<<(DMm * DIi) / 256, 256>>>(out_proj_w, p_wout, DMm * DIi);
    k_round<<<(DMm * DMm) / 256, 256>>>(conv_w, p_wcv, DMm * DMm);

    // 0. transpose x -> xT [m, DM] (rounded)
    k_transpose_x<<<dim3(LL / 32, DMm / 32, BB), tb>>>(x);

    // 1. xz = xT @ in_proj_w^T   [m, 2048]
    k_gemm_ca<128,128,2,4,0,false><<<dim3(2 * DIi / 128, MT / 128), 256, SM_BIG>>>(
        p_xT, DMm, p_w1, p_xz, 2 * DIi, DMm, nullptr);

    // 2. causal depthwise conv1d + silu -> xc (rounded)
    k_conv1d_silu<<<(MT * DIi) / 256, 256>>>(conv1d_w, conv1d_b);

    // 3. x_dbl = xc @ x_proj_w^T  [m, 64] (rounded)
    k_gemm_ca<64,64,4,2,0,true><<<dim3(1, MT / 64), 256, SM_SMALL>>>(
        p_xc, DIi, p_wxp, p_xdbl, 64, DIi, nullptr);

    // 4. dt = softplus(x_dbl[:, :32] @ dt_proj_w^T + b)  [m, 1024]
    k_gemm_ca<128,128,2,4,1,false><<<dim3(DIi / 128, MT / 128), 256, SM_BIG>>>(
        p_xdbl, 64, p_wdt, p_dt, DIi, DTRr, dt_proj_b);

    // 5. chunked selective scan (y rounded)
    k_scanA<<<(CH * BB * DIi * DSs) / 256, 256>>>(A_log);
    k_scanC<<<(BB * DIi * DSs) / 256, 256>>>();
    k_scanB<<<(CH * BB * DIi * DSs) / 256, 256>>>(A_log, Dp);

    // 6. o1 = y @ out_proj_w^T  [m, 512] (rounded)
    k_gemm_ca<128,128,2,4,0,true><<<dim3(DMm / 128, MT / 128), 256, SM_BIG>>>(
        p_y, DIi, p_wout, p_o1, DMm, DIi, nullptr);

    // 7. o2 = gelu(o1 @ conv_w^T + conv_b)  [m, 512]
    k_gemm_ca<128,128,2,4,2,false><<<dim3(DMm / 128, MT / 128), 256, SM_BIG>>>(
        p_o1, DMm, p_wcv, p_o2, DMm, DMm, conv_b);

    // 8. GroupNorm
    k_gn_zero<<<1, 32>>>();
    k_gn_reduce<<<dim3(128, BB), 256>>>();
    k_gn_finalize<<<1, 32>>>();
    k_gn_write<<<dim3(LL / 32, DMm / 32, BB), tb>>>(out, gamma, beta);
}